// round 15
// baseline (speedup 1.0000x reference)
#include <cuda_runtime.h>
#include <cuda_fp16.h>

#define CIN  128
#define CTOT 128   // [mu(64) | logstd(64)]
#define COUT 64
#define NMAX 100000
#define EMAX 2000000
#define MAX_LOGSTD 10.0f

#define XPAD 136   // halves per padded smem row (68 words == 4 mod 32: conflict-free frags)
#define GEMM_SMEM ((64 + 128) * XPAD * 2)

// Scratch (device globals: no allocations allowed)
// g_feat in fp16, row-scaled g = (x @ [Wmu|Wls]) * dinv[row]: 128 halves = 256B
__device__ __align__(16) __half g_feat[(size_t)NMAX * CTOT];
__device__ int   g_cnt [NMAX];                 // in-degree (without self-loop)
__device__ int   g_beg [NMAX];                 // CSR segment start (atomic alloc)
__device__ int   g_cur [NMAX];                 // fill cursors
__device__ int   g_srcs[EMAX];                 // CSR column (src) indices (compact)
__device__ int   g_ctr;                        // global allocation cursor
__device__ int   g_is64;                       // 1 if edge_index really is int64

// L2-cached (L1-bypass) 8-byte load: g_feat rows have ~1% per-SM L1 hit rate
// (25.6MB random working set vs 228KB L1), so L1 allocation is pure overhead.
__device__ __forceinline__ uint2 ldcg_u2(const void* p) {
    uint2 v;
    asm volatile("ld.global.cg.v2.u32 {%0, %1}, [%2];"
                 : "=r"(v.x), "=r"(v.y) : "l"(p));
    return v;
}

// ---------------------------------------------------------------------------
// 0) fused: zero counts/cursor/flag + sampled dtype detect.
//    Detect: read first min(E,64K) slots AS int64 (never OOB under either
//    dtype). Misread-int32 passes [0,N) only if its high word is 0
//    (p ~ 1e-5/slot) -> 64K samples decide with certainty.
__global__ void zde_kernel(const long long* __restrict__ ei, long long cap, int N) {
    long long i = (long long)blockIdx.x * blockDim.x + threadIdx.x;
    if (i == 0) { g_is64 = 1; g_ctr = 0; }
    if (i < N) g_cnt[i] = 0;
    if (i < cap) {
        long long v = ei[i];
        if (v < 0 || v >= N) g_is64 = 0;   // racy same-value write: fine
    }
}

__device__ __forceinline__ int load_idx(const void* ei, long long slot) {
    return g_is64 ? (int)((const long long*)ei)[slot]
                  : ((const int*)ei)[slot];
}

// 1) in-degree count over dst
__global__ void count_kernel(const void* __restrict__ ei, long long E, int N) {
    long long i = (long long)blockIdx.x * blockDim.x + threadIdx.x;
    if (i < E) {
        int dst = load_idx(ei, E + i);
        if ((unsigned)dst < (unsigned)N) atomicAdd(&g_cnt[dst], 1);
    }
}

// 2) CSR segment allocation (order-free scan replacement; warp-aggregated atomic)
__global__ void alloc_kernel(int N) {
    int i = blockIdx.x * blockDim.x + threadIdx.x;
    if (i < N) {
        int c = g_cnt[i];
        int beg = atomicAdd(&g_ctr, c);
        g_beg[i] = beg;
        g_cur[i] = beg;
    }
}

// 3) CSR fill: scatter src indices into dst-grouped segments
__global__ void fill_kernel(const void* __restrict__ ei, long long E, int N) {
    long long i = (long long)blockIdx.x * blockDim.x + threadIdx.x;
    if (i < E) {
        int src = load_idx(ei, i);
        int dst = load_idx(ei, E + i);
        if ((unsigned)src < (unsigned)N && (unsigned)dst < (unsigned)N) {
            int pos = atomicAdd(&g_cur[dst], 1);
            if (pos < EMAX) g_srcs[pos] = src;
        }
    }
}

// 4) Tensor-core GEMM: g_feat[row] = fp16( (x[row] @ [Wmu|Wls]) * dinv[row] )
//    BM=64, BN=128(full), K=128(full). 256 threads = 8 warps in 4(M)x2(N).
//    Forked after count (needs g_cnt for dinv); hidden under alloc+fill.
__global__ __launch_bounds__(256) void gemm_kernel(
    const float* __restrict__ x,
    const float* __restrict__ Wmu,
    const float* __restrict__ Wls,
    int N)
{
    extern __shared__ __half sh[];
    __half* x_s = sh;              // [64][XPAD]
    __half* w_s = sh + 64 * XPAD;  // [128][XPAD]

    const int tid  = threadIdx.x;
    const int row0 = blockIdx.x * 64;

    #pragma unroll
    for (int j = 0; j < 32; j++) {
        int idx = tid + j * 256;          // 8192 = 64*128
        int r = idx >> 7, k = idx & 127;
        int row = row0 + r;
        float v = (row < N) ? x[(size_t)row * CIN + k] : 0.0f;
        x_s[r * XPAD + k] = __float2half_rn(v);
    }
    #pragma unroll
    for (int j = 0; j < 64; j++) {
        int idx = tid + j * 256;          // 16384 = 128*128
        int k = idx >> 7, c = idx & 127;
        float v = (c < 64) ? Wmu[k * 64 + c] : Wls[k * 64 + (c - 64)];
        w_s[c * XPAD + k] = __float2half_rn(v);
    }
    __syncthreads();

    const int w    = tid >> 5;
    const int lane = tid & 31;
    const int wr   = w & 3;
    const int wc   = w >> 2;
    const int g    = lane >> 2;
    const int t    = lane & 3;

    float acc[8][4];
    #pragma unroll
    for (int nt = 0; nt < 8; nt++)
        #pragma unroll
        for (int q = 0; q < 4; q++) acc[nt][q] = 0.0f;

    const __half* xb = x_s + (wr * 16 + g) * XPAD + t * 2;
    const __half* wb = w_s + (wc * 64 + g) * XPAD + t * 2;

    #pragma unroll
    for (int kc = 0; kc < 8; kc++) {
        unsigned a0 = *(const unsigned*)(xb + kc * 16);
        unsigned a1 = *(const unsigned*)(xb + kc * 16 + 8 * XPAD);
        unsigned a2 = *(const unsigned*)(xb + kc * 16 + 8);
        unsigned a3 = *(const unsigned*)(xb + kc * 16 + 8 * XPAD + 8);
        #pragma unroll
        for (int nt = 0; nt < 8; nt++) {
            unsigned b0 = *(const unsigned*)(wb + nt * 8 * XPAD + kc * 16);
            unsigned b1 = *(const unsigned*)(wb + nt * 8 * XPAD + kc * 16 + 8);
            asm volatile(
                "mma.sync.aligned.m16n8k16.row.col.f32.f16.f16.f32 "
                "{%0,%1,%2,%3}, {%4,%5,%6,%7}, {%8,%9}, {%0,%1,%2,%3};"
                : "+f"(acc[nt][0]), "+f"(acc[nt][1]),
                  "+f"(acc[nt][2]), "+f"(acc[nt][3])
                : "r"(a0), "r"(a1), "r"(a2), "r"(a3), "r"(b0), "r"(b1));
        }
    }

    int r1 = row0 + wr * 16 + g;
    int r2 = r1 + 8;
    float d1 = (r1 < N) ? rsqrtf((float)g_cnt[r1] + 1.0f) : 0.0f;
    float d2 = (r2 < N) ? rsqrtf((float)g_cnt[r2] + 1.0f) : 0.0f;
    #pragma unroll
    for (int nt = 0; nt < 8; nt++) {
        int col = wc * 64 + nt * 8 + t * 2;
        if (r1 < N) {
            __half2 h = __floats2half2_rn(acc[nt][0] * d1, acc[nt][1] * d1);
            *(__half2*)(g_feat + (size_t)r1 * CTOT + col) = h;
        }
        if (r2 < N) {
            __half2 h = __floats2half2_rn(acc[nt][2] * d2, acc[nt][3] * d2);
            *(__half2*)(g_feat + (size_t)r2 * CTOT + col) = h;
        }
    }
}

// 5) fused gather + finalize (round-11 form + .cg row loads).
//    One warp per node; lane l owns 4 fp16 features [4l,4l+4) (uint2 = 8B).
//    Lanes 0-15 = mu, 16-31 = logstd.
__global__ __launch_bounds__(256) void gather_kernel(
    const float* __restrict__ b_mu,
    const float* __restrict__ b_ls,
    const float* __restrict__ eps,
    float* __restrict__ out,
    int N)
{
    int node = blockIdx.x * 8 + (threadIdx.x >> 5);
    if (node >= N) return;
    int lane = threadIdx.x & 31;

    int cnt = g_cnt[node];
    int beg = g_beg[node];
    int end = beg + cnt;

    // self-loop
    uint2 r0 = ldcg_u2((const uint2*)(g_feat + (size_t)node * CTOT) + lane);
    float2 f0 = __half22float2(*(__half2*)&r0.x);
    float2 f1 = __half22float2(*(__half2*)&r0.y);
    float4 a = make_float4(f0.x, f0.y, f1.x, f1.y);

    int e = beg;
    for (; e + 8 <= end; e += 8) {       // unroll 8 for MLP
        int s[8];
        #pragma unroll
        for (int u = 0; u < 8; u++) s[u] = g_srcs[e + u];
        uint2 v[8];
        #pragma unroll
        for (int u = 0; u < 8; u++)
            v[u] = ldcg_u2((const uint2*)(g_feat + (size_t)s[u] * CTOT) + lane);
        #pragma unroll
        for (int u = 0; u < 8; u++) {
            float2 g0 = __half22float2(*(__half2*)&v[u].x);
            float2 g1 = __half22float2(*(__half2*)&v[u].y);
            a.x += g0.x; a.y += g0.y; a.z += g1.x; a.w += g1.y;
        }
    }
    for (; e < end; e++) {
        int sidx = g_srcs[e];
        uint2 vv = ldcg_u2((const uint2*)(g_feat + (size_t)sidx * CTOT) + lane);
        float2 g0 = __half22float2(*(__half2*)&vv.x);
        float2 g1 = __half22float2(*(__half2*)&vv.y);
        a.x += g0.x; a.y += g0.y; a.z += g1.x; a.w += g1.y;
    }

    float dinv = rsqrtf((float)cnt + 1.0f);
    float4 b = (lane < 16) ? ((const float4*)b_mu)[lane]
                           : ((const float4*)b_ls)[lane - 16];
    float4 v;
    v.x = a.x * dinv + b.x;
    v.y = a.y * dinv + b.y;
    v.z = a.z * dinv + b.z;
    v.w = a.w * dinv + b.w;

    // exp(min(ls,10)) — meaningful on lanes 16-31; harmless elsewhere (capped)
    float px = expf(fminf(v.x, MAX_LOGSTD));
    float py = expf(fminf(v.y, MAX_LOGSTD));
    float pz = expf(fminf(v.z, MAX_LOGSTD));
    float pw = expf(fminf(v.w, MAX_LOGSTD));
    px = __shfl_down_sync(0xFFFFFFFFu, px, 16);
    py = __shfl_down_sync(0xFFFFFFFFu, py, 16);
    pz = __shfl_down_sync(0xFFFFFFFFu, pz, 16);
    pw = __shfl_down_sync(0xFFFFFFFFu, pw, 16);

    if (lane < 16) {
        float4 e4 = ((const float4*)(eps + (size_t)node * COUT))[lane];
        float4 z;
        z.x = v.x + e4.x * px;
        z.y = v.y + e4.y * py;
        z.z = v.z + e4.z * pz;
        z.w = v.w + e4.w * pw;
        ((float4*)(out + (size_t)node * COUT))[lane] = z;
    }
}

extern "C" void kernel_launch(void* const* d_in, const int* in_sizes, int n_in,
                              void* d_out, int out_size)
{
    const float* x   = (const float*)d_in[0];
    const void*  ei  = d_in[1];                 // int32 or int64, detected on device
    const float* Wmu = (const float*)d_in[2];
    const float* bmu = (const float*)d_in[3];
    const float* Wls = (const float*)d_in[4];
    const float* bls = (const float*)d_in[5];
    const float* eps = (const float*)d_in[6];
    float*       out = (float*)d_out;

    int N = in_sizes[0] / CIN;          // 100000
    long long E = in_sizes[1] / 2;      // 1600000
    long long cap = E < 65536 ? E : 65536;
    long long zde = N > cap ? N : cap;

    // host-side function attribute (not a stream op; graph-capture safe)
    cudaFuncSetAttribute(gemm_kernel,
                         cudaFuncAttributeMaxDynamicSharedMemorySize, GEMM_SMEM);

    // fresh fork/join stream + events each call (deterministic captured work;
    // host-side creation, no tracked device memory)
    cudaStream_t s2;
    cudaEvent_t ev_fork, ev_join;
    cudaStreamCreateWithFlags(&s2, cudaStreamNonBlocking);
    cudaEventCreateWithFlags(&ev_fork, cudaEventDisableTiming);
    cudaEventCreateWithFlags(&ev_join, cudaEventDisableTiming);

    zde_kernel<<<(int)((zde + 255) / 256), 256>>>((const long long*)ei, cap, N);
    count_kernel<<<(int)((E + 255) / 256), 256>>>(ei, E, N);

    // fork: GEMM (needs only g_cnt) runs concurrent with alloc+fill
    cudaEventRecord(ev_fork, 0);
    cudaStreamWaitEvent(s2, ev_fork, 0);
    gemm_kernel<<<(N + 63) / 64, 256, GEMM_SMEM, s2>>>(x, Wmu, Wls, N);
    cudaEventRecord(ev_join, s2);

    alloc_kernel<<<(N + 255) / 256, 256>>>(N);
    fill_kernel<<<(int)((E + 255) / 256), 256>>>(ei, E, N);

    // join: gather needs g_feat (gemm) + CSR (fill)
    cudaStreamWaitEvent(0, ev_join, 0);
    gather_kernel<<<(N + 7) / 8, 256>>>(bmu, bls, eps, out, N);
}

// round 16
// speedup vs baseline: 1.1457x; 1.1457x over previous
#include <cuda_runtime.h>
#include <cuda_fp16.h>

#define CIN  128
#define CTOT 128   // [mu(64) | logstd(64)]
#define COUT 64
#define NMAX 100000
#define EMAX 2000000
#define MAX_LOGSTD 10.0f

#define XPAD 136   // halves per padded smem row (68 words == 4 mod 32: conflict-free frags)
#define GEMM_SMEM ((64 + 128) * XPAD * 2)

// Scratch (device globals: no allocations allowed)
// g_feat in fp16, row-scaled g = (x @ [Wmu|Wls]) * dinv[row]: 128 halves = 256B
__device__ __align__(16) __half g_feat[(size_t)NMAX * CTOT];
__device__ int   g_cnt [NMAX];                 // in-degree (without self-loop)
__device__ int   g_beg [NMAX];                 // CSR segment start (atomic alloc)
__device__ int   g_rank[EMAX];                 // per-edge rank within its dst segment
__device__ int   g_srcs[EMAX];                 // CSR column (src) indices (compact)
__device__ int   g_ctr;                        // global allocation cursor
__device__ int   g_is64;                       // 1 if edge_index really is int64

// ---------------------------------------------------------------------------
// 0) fused: zero counts/cursor/flag + sampled dtype detect.
//    Detect: read first min(E,64K) slots AS int64 (never OOB under either
//    dtype). Misread-int32 passes [0,N) only if its high word is 0
//    (p ~ 1e-5/slot) -> 64K samples decide with certainty.
__global__ void zde_kernel(const long long* __restrict__ ei, long long cap, int N) {
    long long i = (long long)blockIdx.x * blockDim.x + threadIdx.x;
    if (i == 0) { g_is64 = 1; g_ctr = 0; }
    if (i < N) g_cnt[i] = 0;
    if (i < cap) {
        long long v = ei[i];
        if (v < 0 || v >= N) g_is64 = 0;   // racy same-value write: fine
    }
}

__device__ __forceinline__ int load_idx(const void* ei, long long slot) {
    return g_is64 ? (int)((const long long*)ei)[slot]
                  : ((const int*)ei)[slot];
}

// 1) in-degree count over dst; ALSO records each edge's rank within its dst
//    segment (the atomic's return value, previously discarded). This is what
//    lets fill_kernel run atomic-free.
__global__ void count_kernel(const void* __restrict__ ei, long long E, int N) {
    long long i = (long long)blockIdx.x * blockDim.x + threadIdx.x;
    if (i < E) {
        int dst = load_idx(ei, E + i);
        int r = -1;
        if ((unsigned)dst < (unsigned)N) r = atomicAdd(&g_cnt[dst], 1);
        g_rank[i] = r;
    }
}

// 2) CSR segment allocation (order-free scan replacement; warp-aggregated atomic)
__global__ void alloc_kernel(int N) {
    int i = blockIdx.x * blockDim.x + threadIdx.x;
    if (i < N) {
        int c = g_cnt[i];
        g_beg[i] = atomicAdd(&g_ctr, c);
    }
}

// 3) CSR fill, ATOMIC-FREE: slot = g_beg[dst] + rank (unique by construction)
__global__ void fill_kernel(const void* __restrict__ ei, long long E, int N) {
    long long i = (long long)blockIdx.x * blockDim.x + threadIdx.x;
    if (i < E) {
        int src = load_idx(ei, i);
        int dst = load_idx(ei, E + i);
        int r   = g_rank[i];
        if ((unsigned)src < (unsigned)N && (unsigned)dst < (unsigned)N && r >= 0) {
            long long pos = (long long)g_beg[dst] + r;
            if (pos < EMAX) g_srcs[pos] = src;
        }
    }
}

// 4) Tensor-core GEMM: g_feat[row] = fp16( (x[row] @ [Wmu|Wls]) * dinv[row] )
//    BM=64, BN=128(full), K=128(full). 256 threads = 8 warps in 4(M)x2(N).
//    Forked after count (needs g_cnt for dinv); hidden under alloc+fill.
__global__ __launch_bounds__(256) void gemm_kernel(
    const float* __restrict__ x,
    const float* __restrict__ Wmu,
    const float* __restrict__ Wls,
    int N)
{
    extern __shared__ __half sh[];
    __half* x_s = sh;              // [64][XPAD]
    __half* w_s = sh + 64 * XPAD;  // [128][XPAD]

    const int tid  = threadIdx.x;
    const int row0 = blockIdx.x * 64;

    #pragma unroll
    for (int j = 0; j < 32; j++) {
        int idx = tid + j * 256;          // 8192 = 64*128
        int r = idx >> 7, k = idx & 127;
        int row = row0 + r;
        float v = (row < N) ? x[(size_t)row * CIN + k] : 0.0f;
        x_s[r * XPAD + k] = __float2half_rn(v);
    }
    #pragma unroll
    for (int j = 0; j < 64; j++) {
        int idx = tid + j * 256;          // 16384 = 128*128
        int k = idx >> 7, c = idx & 127;
        float v = (c < 64) ? Wmu[k * 64 + c] : Wls[k * 64 + (c - 64)];
        w_s[c * XPAD + k] = __float2half_rn(v);
    }
    __syncthreads();

    const int w    = tid >> 5;
    const int lane = tid & 31;
    const int wr   = w & 3;
    const int wc   = w >> 2;
    const int g    = lane >> 2;
    const int t    = lane & 3;

    float acc[8][4];
    #pragma unroll
    for (int nt = 0; nt < 8; nt++)
        #pragma unroll
        for (int q = 0; q < 4; q++) acc[nt][q] = 0.0f;

    const __half* xb = x_s + (wr * 16 + g) * XPAD + t * 2;
    const __half* wb = w_s + (wc * 64 + g) * XPAD + t * 2;

    #pragma unroll
    for (int kc = 0; kc < 8; kc++) {
        unsigned a0 = *(const unsigned*)(xb + kc * 16);
        unsigned a1 = *(const unsigned*)(xb + kc * 16 + 8 * XPAD);
        unsigned a2 = *(const unsigned*)(xb + kc * 16 + 8);
        unsigned a3 = *(const unsigned*)(xb + kc * 16 + 8 * XPAD + 8);
        #pragma unroll
        for (int nt = 0; nt < 8; nt++) {
            unsigned b0 = *(const unsigned*)(wb + nt * 8 * XPAD + kc * 16);
            unsigned b1 = *(const unsigned*)(wb + nt * 8 * XPAD + kc * 16 + 8);
            asm volatile(
                "mma.sync.aligned.m16n8k16.row.col.f32.f16.f16.f32 "
                "{%0,%1,%2,%3}, {%4,%5,%6,%7}, {%8,%9}, {%0,%1,%2,%3};"
                : "+f"(acc[nt][0]), "+f"(acc[nt][1]),
                  "+f"(acc[nt][2]), "+f"(acc[nt][3])
                : "r"(a0), "r"(a1), "r"(a2), "r"(a3), "r"(b0), "r"(b1));
        }
    }

    int r1 = row0 + wr * 16 + g;
    int r2 = r1 + 8;
    float d1 = (r1 < N) ? rsqrtf((float)g_cnt[r1] + 1.0f) : 0.0f;
    float d2 = (r2 < N) ? rsqrtf((float)g_cnt[r2] + 1.0f) : 0.0f;
    #pragma unroll
    for (int nt = 0; nt < 8; nt++) {
        int col = wc * 64 + nt * 8 + t * 2;
        if (r1 < N) {
            __half2 h = __floats2half2_rn(acc[nt][0] * d1, acc[nt][1] * d1);
            *(__half2*)(g_feat + (size_t)r1 * CTOT + col) = h;
        }
        if (r2 < N) {
            __half2 h = __floats2half2_rn(acc[nt][2] * d2, acc[nt][3] * d2);
            *(__half2*)(g_feat + (size_t)r2 * CTOT + col) = h;
        }
    }
}

// 5) fused gather + finalize (round-11 form, untouched — local optimum).
//    One warp per node; lane l owns 4 fp16 features [4l,4l+4) (uint2 = 8B).
//    Lanes 0-15 = mu, 16-31 = logstd.
__global__ __launch_bounds__(256) void gather_kernel(
    const float* __restrict__ b_mu,
    const float* __restrict__ b_ls,
    const float* __restrict__ eps,
    float* __restrict__ out,
    int N)
{
    int node = blockIdx.x * 8 + (threadIdx.x >> 5);
    if (node >= N) return;
    int lane = threadIdx.x & 31;

    int cnt = g_cnt[node];
    int beg = g_beg[node];
    int end = beg + cnt;

    // self-loop
    uint2 r0 = ((const uint2*)(g_feat + (size_t)node * CTOT))[lane];
    float2 f0 = __half22float2(*(__half2*)&r0.x);
    float2 f1 = __half22float2(*(__half2*)&r0.y);
    float4 a = make_float4(f0.x, f0.y, f1.x, f1.y);

    int e = beg;
    for (; e + 8 <= end; e += 8) {       // unroll 8 for MLP
        int s[8];
        #pragma unroll
        for (int u = 0; u < 8; u++) s[u] = g_srcs[e + u];
        uint2 v[8];
        #pragma unroll
        for (int u = 0; u < 8; u++)
            v[u] = ((const uint2*)(g_feat + (size_t)s[u] * CTOT))[lane];
        #pragma unroll
        for (int u = 0; u < 8; u++) {
            float2 g0 = __half22float2(*(__half2*)&v[u].x);
            float2 g1 = __half22float2(*(__half2*)&v[u].y);
            a.x += g0.x; a.y += g0.y; a.z += g1.x; a.w += g1.y;
        }
    }
    for (; e < end; e++) {
        int sidx = g_srcs[e];
        uint2 vv = ((const uint2*)(g_feat + (size_t)sidx * CTOT))[lane];
        float2 g0 = __half22float2(*(__half2*)&vv.x);
        float2 g1 = __half22float2(*(__half2*)&vv.y);
        a.x += g0.x; a.y += g0.y; a.z += g1.x; a.w += g1.y;
    }

    float dinv = rsqrtf((float)cnt + 1.0f);
    float4 b = (lane < 16) ? ((const float4*)b_mu)[lane]
                           : ((const float4*)b_ls)[lane - 16];
    float4 v;
    v.x = a.x * dinv + b.x;
    v.y = a.y * dinv + b.y;
    v.z = a.z * dinv + b.z;
    v.w = a.w * dinv + b.w;

    // exp(min(ls,10)) — meaningful on lanes 16-31; harmless elsewhere (capped)
    float px = expf(fminf(v.x, MAX_LOGSTD));
    float py = expf(fminf(v.y, MAX_LOGSTD));
    float pz = expf(fminf(v.z, MAX_LOGSTD));
    float pw = expf(fminf(v.w, MAX_LOGSTD));
    px = __shfl_down_sync(0xFFFFFFFFu, px, 16);
    py = __shfl_down_sync(0xFFFFFFFFu, py, 16);
    pz = __shfl_down_sync(0xFFFFFFFFu, pz, 16);
    pw = __shfl_down_sync(0xFFFFFFFFu, pw, 16);

    if (lane < 16) {
        float4 e4 = ((const float4*)(eps + (size_t)node * COUT))[lane];
        float4 z;
        z.x = v.x + e4.x * px;
        z.y = v.y + e4.y * py;
        z.z = v.z + e4.z * pz;
        z.w = v.w + e4.w * pw;
        ((float4*)(out + (size_t)node * COUT))[lane] = z;
    }
}

extern "C" void kernel_launch(void* const* d_in, const int* in_sizes, int n_in,
                              void* d_out, int out_size)
{
    const float* x   = (const float*)d_in[0];
    const void*  ei  = d_in[1];                 // int32 or int64, detected on device
    const float* Wmu = (const float*)d_in[2];
    const float* bmu = (const float*)d_in[3];
    const float* Wls = (const float*)d_in[4];
    const float* bls = (const float*)d_in[5];
    const float* eps = (const float*)d_in[6];
    float*       out = (float*)d_out;

    int N = in_sizes[0] / CIN;          // 100000
    long long E = in_sizes[1] / 2;      // 1600000
    long long cap = E < 65536 ? E : 65536;
    long long zde = N > cap ? N : cap;

    // host-side function attribute (not a stream op; graph-capture safe)
    cudaFuncSetAttribute(gemm_kernel,
                         cudaFuncAttributeMaxDynamicSharedMemorySize, GEMM_SMEM);

    // fresh fork/join stream + events each call (deterministic captured work;
    // host-side creation, no tracked device memory)
    cudaStream_t s2;
    cudaEvent_t ev_fork, ev_join;
    cudaStreamCreateWithFlags(&s2, cudaStreamNonBlocking);
    cudaEventCreateWithFlags(&ev_fork, cudaEventDisableTiming);
    cudaEventCreateWithFlags(&ev_join, cudaEventDisableTiming);

    zde_kernel<<<(int)((zde + 255) / 256), 256>>>((const long long*)ei, cap, N);
    count_kernel<<<(int)((E + 255) / 256), 256>>>(ei, E, N);

    // fork: GEMM (needs only g_cnt) runs concurrent with alloc+fill
    cudaEventRecord(ev_fork, 0);
    cudaStreamWaitEvent(s2, ev_fork, 0);
    gemm_kernel<<<(N + 63) / 64, 256, GEMM_SMEM, s2>>>(x, Wmu, Wls, N);
    cudaEventRecord(ev_join, s2);

    alloc_kernel<<<(N + 255) / 256, 256>>>(N);
    fill_kernel<<<(int)((E + 255) / 256), 256>>>(ei, E, N);

    // join: gather needs g_feat (gemm) + CSR (fill)
    cudaStreamWaitEvent(0, ev_join, 0);
    gather_kernel<<<(N + 7) / 8, 256>>>(bmu, bls, eps, out, N);
}